// round 1
// baseline (speedup 1.0000x reference)
#include <cuda_runtime.h>

#define NN 50000
#define NE 1600000

struct __align__(8) EP { int s; float w; };

// ---------------- scratch (device globals; no allocations) ----------------
__device__ float g_degW[NN];
__device__ float g_dinv[NN];
__device__ int   g_cnt[NN];
__device__ int   g_rowptr[NN + 1];
__device__ int   g_wp[NN];
__device__ EP    g_ep[NE];
__device__ __align__(16) float g_TX[4][NN * 32];   // Tx1..Tx4 (Tx0 = layer input)
__device__ __align__(16) float g_h[NN * 32];       // layer output (reused)
__device__ __align__(16) float g_CX[NN * 96];      // gate preactivations (i,c,o)
__device__ __align__(16) float g_Wp[2][96 * 164];  // packed transposed weights [o][j], pad 164
__device__ float g_bp[2][96];                      // folded biases per gate-output
__device__ __align__(16) float g_weff[32];         // folded head weight
__device__ float g_beff;                           // folded head bias

__device__ __forceinline__ const float* sel_ptr(int sel, const float* xext) {
    if (sel == 9) return xext;
    if (sel == 4) return g_h;
    return g_TX[sel];
}

__device__ __forceinline__ float fsig(float x) {
    return 1.f / (1.f + __expf(-x));
}
__device__ __forceinline__ float ftanh(float x) {
    x = fminf(fmaxf(x, -15.f), 15.f);
    float t = __expf(2.f * x);
    return (t - 1.f) / (t + 1.f);
}

// ---------------- CSR build ----------------
__global__ void k_zero() {
    int i = blockIdx.x * blockDim.x + threadIdx.x;
    if (i < NN) { g_degW[i] = 0.f; g_cnt[i] = 0; }
}

__global__ void k_degree(const int* __restrict__ ei, const float* __restrict__ ew) {
    int e = blockIdx.x * blockDim.x + threadIdx.x;
    if (e >= NE) return;
    atomicAdd(&g_degW[ei[e]], ew[e]);       // deg by SRC (weighted)
    atomicAdd(&g_cnt[ei[NE + e]], 1);       // in-degree count by DST
}

__global__ void k_dinv() {
    int i = blockIdx.x * blockDim.x + threadIdx.x;
    if (i >= NN) return;
    float d = g_degW[i];
    g_dinv[i] = (d > 0.f) ? rsqrtf(fmaxf(d, 1e-12f)) : 0.f;
}

__global__ void k_scan() {   // single block, 1024 threads, exclusive scan of g_cnt
    __shared__ int sh[1024];
    int t = threadIdx.x;
    const int C = (NN + 1023) / 1024;
    int base = t * C;
    int local = 0;
    for (int i = 0; i < C; i++) { int idx = base + i; if (idx < NN) local += g_cnt[idx]; }
    sh[t] = local;
    __syncthreads();
    for (int off = 1; off < 1024; off <<= 1) {
        int v = 0;
        if (t >= off) v = sh[t - off];
        __syncthreads();
        sh[t] += v;
        __syncthreads();
    }
    int run = (t == 0) ? 0 : sh[t - 1];
    for (int i = 0; i < C; i++) {
        int idx = base + i;
        if (idx < NN) { g_rowptr[idx] = run; g_wp[idx] = run; run += g_cnt[idx]; }
    }
    if (t == 1023) g_rowptr[NN] = sh[1023];
}

__global__ void k_scatter(const int* __restrict__ ei, const float* __restrict__ ew) {
    int e = blockIdx.x * blockDim.x + threadIdx.x;
    if (e >= NE) return;
    int s = ei[e], d = ei[NE + e];
    int pos = atomicAdd(&g_wp[d], 1);
    EP p;
    p.s = s;
    p.w = -g_dinv[s] * ew[e] * g_dinv[d];
    g_ep[pos] = p;
}

// ---------------- weight / head prep ----------------
__global__ void k_prepw(const float* __restrict__ Wx, const float* __restrict__ bx,
                        const float* __restrict__ bh, const float* __restrict__ bb,
                        int layer) {
    int idx = blockIdx.x * blockDim.x + threadIdx.x;
    if (idx >= 96 * 160) return;
    int o = idx / 160, j = idx % 160;
    int gi = o >> 5, f = o & 31;
    int g = (gi == 0) ? 0 : ((gi == 1) ? 2 : 3);   // gates i, c, o  (forget gate dead)
    int k = j >> 5, jj = j & 31;
    g_Wp[layer][o * 164 + j] = Wx[(((g * 5 + k) * 32) + jj) * 32 + f];
    if (j == 0) g_bp[layer][o] = bx[g * 32 + f] + bh[g * 32 + f] + bb[g * 32 + f];
}

__global__ void k_headfold(const float* __restrict__ hw1, const float* __restrict__ hb1,
                           const float* __restrict__ hw2, const float* __restrict__ hb2,
                           const float* __restrict__ hw3, const float* __restrict__ hb3,
                           const float* __restrict__ hw4, const float* __restrict__ hb4) {
    int r = threadIdx.x;   // 32 threads
    float t1r[16], t2r[8], t3r[4];
    for (int c = 0; c < 16; c++) t1r[c] = hw1[r * 16 + c];
    for (int c = 0; c < 8; c++) {
        float s = 0.f;
        for (int i = 0; i < 16; i++) s += t1r[i] * hw2[i * 8 + c];
        t2r[c] = s;
    }
    for (int c = 0; c < 4; c++) {
        float s = 0.f;
        for (int i = 0; i < 8; i++) s += t2r[i] * hw3[i * 4 + c];
        t3r[c] = s;
    }
    float we = 0.f;
    for (int i = 0; i < 4; i++) we += t3r[i] * hw4[i];
    g_weff[r] = we;
    if (r == 0) {
        float v2[8], v3[4];
        for (int c = 0; c < 8; c++) {
            float s = hb2[c];
            for (int i = 0; i < 16; i++) s += hb1[i] * hw2[i * 8 + c];
            v2[c] = s;
        }
        for (int c = 0; c < 4; c++) {
            float s = hb3[c];
            for (int i = 0; i < 8; i++) s += v2[i] * hw3[i * 4 + c];
            v3[c] = s;
        }
        float b = hb4[0];
        for (int i = 0; i < 4; i++) b += v3[i] * hw4[i];
        g_beff = b;
    }
}

// ---------------- sparse propagation: out = (2?) * P @ xin (- prev) ----------------
template <bool SUB>
__global__ void k_prop(const float* __restrict__ xext, int insel, int prevsel, int outsel) {
    int gw = (blockIdx.x * blockDim.x + threadIdx.x) >> 5;
    int lane = threadIdx.x & 31;
    if (gw >= NN) return;
    const float* xin = sel_ptr(insel, xext);
    int beg = g_rowptr[gw], end = g_rowptr[gw + 1];
    float acc = 0.f;
    int e = beg;
#pragma unroll 1
    for (; e + 4 <= end; e += 4) {
        EP p0 = g_ep[e], p1 = g_ep[e + 1], p2 = g_ep[e + 2], p3 = g_ep[e + 3];
        float x0 = xin[p0.s * 32 + lane];
        float x1 = xin[p1.s * 32 + lane];
        float x2 = xin[p2.s * 32 + lane];
        float x3 = xin[p3.s * 32 + lane];
        acc = fmaf(p0.w, x0, acc);
        acc = fmaf(p1.w, x1, acc);
        acc = fmaf(p2.w, x2, acc);
        acc = fmaf(p3.w, x3, acc);
    }
    for (; e < end; ++e) {
        EP p = g_ep[e];
        acc = fmaf(p.w, xin[p.s * 32 + lane], acc);
    }
    int o = gw * 32 + lane;
    if (SUB) {
        const float* prev = sel_ptr(prevsel, xext);
        g_TX[outsel][o] = 2.f * acc - prev[o];
    } else {
        g_TX[outsel][o] = acc;
    }
}

// ---------------- dense Chebyshev GEMM: CX[n][96] = bias + sum_j TX[n][j] * Wp[j][o] ----------------
__global__ void __launch_bounds__(128) k_gemm(const float* __restrict__ xext, int insel, int layer) {
    int w = threadIdx.x >> 5, lane = threadIdx.x & 31;
    int n0 = blockIdx.x * 16 + w * 4;
    if (n0 >= NN) return;
    const float* p0 = sel_ptr(insel, xext);
    const float* planes[5] = {p0, g_TX[0], g_TX[1], g_TX[2], g_TX[3]};
    const float* W = g_Wp[layer];
    const float* bp = g_bp[layer];
    float b0 = bp[lane], b1 = bp[lane + 32], b2 = bp[lane + 64];
    float a[4][3];
#pragma unroll
    for (int t = 0; t < 4; t++) { a[t][0] = b0; a[t][1] = b1; a[t][2] = b2; }
    const float* Wr0 = W + lane * 164;
    const float* Wr1 = W + (lane + 32) * 164;
    const float* Wr2 = W + (lane + 64) * 164;
#pragma unroll
    for (int k = 0; k < 5; k++) {
        const float* pk = planes[k];
#pragma unroll
        for (int jj = 0; jj < 32; jj += 4) {
            int j = k * 32 + jj;
            float4 w0 = *(const float4*)(Wr0 + j);
            float4 w1 = *(const float4*)(Wr1 + j);
            float4 w2 = *(const float4*)(Wr2 + j);
#pragma unroll
            for (int t = 0; t < 4; t++) {
                float4 xv = *(const float4*)(pk + (n0 + t) * 32 + jj);
                a[t][0] = fmaf(xv.x, w0.x, fmaf(xv.y, w0.y, fmaf(xv.z, w0.z, fmaf(xv.w, w0.w, a[t][0]))));
                a[t][1] = fmaf(xv.x, w1.x, fmaf(xv.y, w1.y, fmaf(xv.z, w1.z, fmaf(xv.w, w1.w, a[t][1]))));
                a[t][2] = fmaf(xv.x, w2.x, fmaf(xv.y, w2.y, fmaf(xv.z, w2.z, fmaf(xv.w, w2.w, a[t][2]))));
            }
        }
    }
#pragma unroll
    for (int t = 0; t < 4; t++) {
        float* o = g_CX + (n0 + t) * 96;
        o[lane] = a[t][0];
        o[lane + 32] = a[t][1];
        o[lane + 64] = a[t][2];
    }
}

// ---------------- gates (H=C=0 simplified GConvLSTM) + ReLU ----------------
__global__ void k_gates(const float* __restrict__ wc) {
    int idx = blockIdx.x * blockDim.x + threadIdx.x;
    if (idx >= NN * 32) return;
    int n = idx >> 5, f = idx & 31;
    const float* c = g_CX + n * 96;
    float I  = fsig(c[f]);
    float Cn = I * ftanh(c[32 + f]);
    float O  = fsig(c[64 + f] + wc[64 + f] * Cn);   // wc[2] row at offset 64
    float h  = O * ftanh(Cn);
    g_h[idx] = fmaxf(h, 0.f);
}

// ---------------- folded head ----------------
__global__ void k_head(float* __restrict__ out) {
    int n = blockIdx.x * blockDim.x + threadIdx.x;
    if (n >= NN) return;
    const float4* h4 = (const float4*)(g_h + n * 32);
    const float4* w4 = (const float4*)g_weff;
    float acc = 0.f;
#pragma unroll
    for (int i = 0; i < 8; i++) {
        float4 a = h4[i], b = w4[i];
        acc += a.x * b.x + a.y * b.y + a.z * b.z + a.w * b.w;
    }
    out[n] = acc + g_beff;
}

// ---------------- launch ----------------
extern "C" void kernel_launch(void* const* d_in, const int* in_sizes, int n_in,
                              void* d_out, int out_size) {
    const float* x     = (const float*)d_in[0];
    const int*   ei    = (const int*)d_in[1];
    const float* ew    = (const float*)d_in[2];
    const float* l1_Wx = (const float*)d_in[3];
    const float* l1_bx = (const float*)d_in[4];
    const float* l1_bh = (const float*)d_in[6];
    const float* l1_wc = (const float*)d_in[7];
    const float* l1_b  = (const float*)d_in[8];
    const float* l2_Wx = (const float*)d_in[9];
    const float* l2_bx = (const float*)d_in[10];
    const float* l2_bh = (const float*)d_in[12];
    const float* l2_wc = (const float*)d_in[13];
    const float* l2_b  = (const float*)d_in[14];
    const float* hw1   = (const float*)d_in[15];
    const float* hb1   = (const float*)d_in[16];
    const float* hw2   = (const float*)d_in[17];
    const float* hb2   = (const float*)d_in[18];
    const float* hw3   = (const float*)d_in[19];
    const float* hb3   = (const float*)d_in[20];
    const float* hw4   = (const float*)d_in[21];
    const float* hb4   = (const float*)d_in[22];
    float* out = (float*)d_out;

    const int NB_N = (NN + 255) / 256;     // 196
    const int NB_E = (NE + 255) / 256;     // 6250
    const int NB_W = NB_E;                 // 50000 warps / 8 per block = 6250
    const int NB_G = NN / 16;              // 3125

    // graph normalization + CSR build (once; shared by all 8 propagations)
    k_zero<<<NB_N, 256>>>();
    k_degree<<<NB_E, 256>>>(ei, ew);
    k_dinv<<<NB_N, 256>>>();
    k_scan<<<1, 1024>>>();
    k_scatter<<<NB_E, 256>>>(ei, ew);

    // weight packing + head folding
    k_prepw<<<60, 256>>>(l1_Wx, l1_bx, l1_bh, l1_b, 0);
    k_prepw<<<60, 256>>>(l2_Wx, l2_bx, l2_bh, l2_b, 1);
    k_headfold<<<1, 32>>>(hw1, hb1, hw2, hb2, hw3, hb3, hw4, hb4);

    // layer 1 (input = x, sel 9)
    k_prop<false><<<NB_W, 256>>>(x, 9, -1, 0);
    k_prop<true ><<<NB_W, 256>>>(x, 0, 9, 1);
    k_prop<true ><<<NB_W, 256>>>(x, 1, 0, 2);
    k_prop<true ><<<NB_W, 256>>>(x, 2, 1, 3);
    k_gemm<<<NB_G, 128>>>(x, 9, 0);
    k_gates<<<NB_E, 256>>>(l1_wc);

    // layer 2 (input = g_h, sel 4)
    k_prop<false><<<NB_W, 256>>>(x, 4, -1, 0);
    k_prop<true ><<<NB_W, 256>>>(x, 0, 4, 1);
    k_prop<true ><<<NB_W, 256>>>(x, 1, 0, 2);
    k_prop<true ><<<NB_W, 256>>>(x, 2, 1, 3);
    k_gemm<<<NB_G, 128>>>(x, 4, 1);
    k_gates<<<NB_E, 256>>>(l2_wc);

    // folded head
    k_head<<<NB_N, 256>>>(out);
}